// round 1
// baseline (speedup 1.0000x reference)
#include <cuda_runtime.h>
#include <cstdint>

// ---------------------------------------------------------------------------
// DynamicFixedQuantizer: sigma selection (global count reduction) + JAX-exact
// threefry2x32 stochastic rounding (partitionable mode: bits[i] = o0^o1 of
// block(key, x0=0, x1=i)).
// ---------------------------------------------------------------------------

__device__ unsigned int g_over;
__device__ unsigned int g_under;
__device__ float g_sigma;
__device__ float g_inv;
__device__ float g_tmin;
__device__ float g_tmax;

// Thresholds from sigma0 = 2^(6-8) = 0.25, bit=8, half=128:
//   t_max0 = 0.25*128 - 0.25 = 31.75 ; t_min0 = -32
//   0.5*t_max0 = 15.875      ; 0.5*t_min0 = -16
#define T_MAX0   31.75f
#define T_MIN0  (-32.0f)
#define HT_MAX0  15.875f
#define HT_MIN0 (-16.0f)

__global__ void zero_kernel() { g_over = 0u; g_under = 0u; }

__device__ __forceinline__ void count4(float4 v, int& over, int& under) {
    over  += (v.x > T_MAX0)  + (v.x < T_MIN0);
    under += (v.x > HT_MAX0) + (v.x < HT_MIN0);
    over  += (v.y > T_MAX0)  + (v.y < T_MIN0);
    under += (v.y > HT_MAX0) + (v.y < HT_MIN0);
    over  += (v.z > T_MAX0)  + (v.z < T_MIN0);
    under += (v.z > HT_MAX0) + (v.z < HT_MIN0);
    over  += (v.w > T_MAX0)  + (v.w < T_MIN0);
    under += (v.w > HT_MAX0) + (v.w < HT_MIN0);
}

__global__ void __launch_bounds__(256) count_kernel(const float4* __restrict__ x4,
                                                    int nquads) {
    int tid    = blockIdx.x * blockDim.x + threadIdx.x;
    int stride = gridDim.x * blockDim.x;
    int over = 0, under = 0;

    int i = tid;
    for (; i + 3 * stride < nquads; i += 4 * stride) {
        float4 a = x4[i];
        float4 b = x4[i + stride];
        float4 c = x4[i + 2 * stride];
        float4 d = x4[i + 3 * stride];
        count4(a, over, under);
        count4(b, over, under);
        count4(c, over, under);
        count4(d, over, under);
    }
    for (; i < nquads; i += stride) {
        count4(x4[i], over, under);
    }

    over  = __reduce_add_sync(0xffffffffu, over);
    under = __reduce_add_sync(0xffffffffu, under);

    __shared__ int so[8], su[8];
    int warp = threadIdx.x >> 5;
    int lane = threadIdx.x & 31;
    if (lane == 0) { so[warp] = over; su[warp] = under; }
    __syncthreads();
    if (threadIdx.x == 0) {
        int o = 0, u = 0;
#pragma unroll
        for (int w = 0; w < 8; w++) { o += so[w]; u += su[w]; }
        atomicAdd(&g_over,  (unsigned)o);
        atomicAdd(&g_under, (unsigned)u);
    }
}

__global__ void decide_kernel(float n) {
    // Matches: overflow = counts.astype(f32)/n ; where(overflow > r_max, s*2,
    //          where(underflow < r_max, s*0.5, s)); then recompute t_min/t_max.
    float overflow  = __uint2float_rn(g_over)  / n;
    float underflow = __uint2float_rn(g_under) / n;
    float sigma = 0.25f;
    if (overflow > 0.01f)       sigma = 0.5f;
    else if (underflow < 0.01f) sigma = 0.125f;
    g_sigma = sigma;
    g_inv   = 1.0f / sigma;            // exact: sigma is a power of two
    g_tmax  = sigma * 128.0f - sigma;
    g_tmin  = -(sigma * 128.0f);
}

// --- JAX threefry2x32 (20 rounds) ------------------------------------------
__device__ __forceinline__ void threefry_block(uint32_t k0, uint32_t k1, uint32_t ks2,
                                               uint32_t x0, uint32_t x1,
                                               uint32_t& o0, uint32_t& o1) {
    x0 += k0; x1 += k1;
#define TF_R(r) { x0 += x1; x1 = __funnelshift_l(x1, x1, (r)); x1 ^= x0; }
    TF_R(13) TF_R(15) TF_R(26) TF_R(6)
    x0 += k1;  x1 += ks2 + 1u;
    TF_R(17) TF_R(29) TF_R(16) TF_R(24)
    x0 += ks2; x1 += k0 + 2u;
    TF_R(13) TF_R(15) TF_R(26) TF_R(6)
    x0 += k0;  x1 += k1 + 3u;
    TF_R(17) TF_R(29) TF_R(16) TF_R(24)
    x0 += k1;  x1 += ks2 + 4u;
    TF_R(13) TF_R(15) TF_R(26) TF_R(6)
    x0 += ks2; x1 += k0 + 5u;
#undef TF_R
    o0 = x0; o1 = x1;
}

__global__ void __launch_bounds__(256) quantize_kernel(const float* __restrict__ x,
                                                       float* __restrict__ out,
                                                       uint32_t k0, uint32_t k1,
                                                       int n) {
    int t = blockIdx.x * blockDim.x + threadIdx.x;
    int j = t << 2;
    if (j >= n) return;

    const uint32_t ks2 = k0 ^ k1 ^ 0x1BD11BDAu;
    const float sigma = g_sigma;
    const float inv   = g_inv;
    const float tmin  = g_tmin;
    const float tmax  = g_tmax;

    float4 v = *reinterpret_cast<const float4*>(x + j);
    float4 q;

#pragma unroll
    for (int c = 0; c < 4; c++) {
        uint32_t o0, o1;
        // partitionable mode: counter hi word = 0 (size < 2^32), lo word = index
        threefry_block(k0, k1, ks2, 0u, (uint32_t)(j + c), o0, o1);
        uint32_t bits = o0 ^ o1;
        // JAX uniform[0,1): bitcast((bits>>9) | 0x3f800000) - 1.0
        float u = __uint_as_float((bits >> 9) | 0x3f800000u) - 1.0f;
        float a = (&v.x)[c];
        // floor(a/sigma + u) * sigma, clip(t_min, t_max).
        // a/sigma == a*inv exactly (sigma is a power of two). No FMA contraction.
        float s  = __fadd_rn(__fmul_rn(a, inv), u);
        float qv = floorf(s) * sigma;
        qv = fminf(fmaxf(qv, tmin), tmax);
        (&q.x)[c] = qv;
    }
    *reinterpret_cast<float4*>(out + j) = q;
}

// --- host-side threefry for key fold ---------------------------------------
static void h_threefry(uint32_t k0, uint32_t k1, uint32_t x0, uint32_t x1,
                       uint32_t& o0, uint32_t& o1) {
    auto rotl = [](uint32_t v, int r) { return (v << r) | (v >> (32 - r)); };
    uint32_t ks[3] = { k0, k1, k0 ^ k1 ^ 0x1BD11BDAu };
    const int R[2][4] = { {13, 15, 26, 6}, {17, 29, 16, 24} };
    x0 += ks[0]; x1 += ks[1];
    for (int i = 0; i < 5; i++) {
        for (int jj = 0; jj < 4; jj++) {
            x0 += x1; x1 = rotl(x1, R[i % 2][jj]); x1 ^= x0;
        }
        x0 += ks[(i + 1) % 3];
        x1 += ks[(i + 2) % 3] + (uint32_t)(i + 1);
    }
    o0 = x0; o1 = x1;
}

extern "C" void kernel_launch(void* const* d_in, const int* in_sizes, int n_in,
                              void* d_out, int out_size) {
    const float* x = (const float*)d_in[0];
    float* out = (float*)d_out;
    int n = in_sizes[0];           // 32*2048*2048 = 134217728

    // key = fold_in(key(42), 0): threefry_2x32(key=[0,42], count=[0,0])
    uint32_t fk0, fk1;
    h_threefry(0u, 42u, 0u, 0u, fk0, fk1);

    zero_kernel<<<1, 1>>>();

    int nquads = n >> 2;
    count_kernel<<<2048, 256>>>((const float4*)x, nquads);

    decide_kernel<<<1, 1>>>((float)n);

    int qthreads = (n + 3) >> 2;
    int qblocks = (qthreads + 255) / 256;
    quantize_kernel<<<qblocks, 256>>>(x, out, fk0, fk1, n);
}

// round 2
// speedup vs baseline: 1.0563x; 1.0563x over previous
#include <cuda_runtime.h>
#include <cstdint>

// ---------------------------------------------------------------------------
// DynamicFixedQuantizer: fused count+decide (last-block pattern) + JAX-exact
// threefry2x32 stochastic rounding, with threefry adds forced onto the fma
// pipe (IMAD via opaque multiply-by-one) to relieve the saturated alu pipe.
// ---------------------------------------------------------------------------

__device__ unsigned int g_over  = 0u;
__device__ unsigned int g_under = 0u;
__device__ unsigned int g_done  = 0u;
__device__ float4 g_qp;   // x=sigma, y=1/sigma, z=tmin, w=tmax

// Thresholds from sigma0 = 2^(6-8) = 0.25, bit=8, half=128:
#define T_MAX0   31.75f
#define T_MIN0  (-32.0f)
#define HT_MAX0  15.875f
#define HT_MIN0 (-16.0f)

__device__ __forceinline__ void count4(float4 v, int& over, int& under) {
    over  += (v.x > T_MAX0)  + (v.x < T_MIN0);
    under += (v.x > HT_MAX0) + (v.x < HT_MIN0);
    over  += (v.y > T_MAX0)  + (v.y < T_MIN0);
    under += (v.y > HT_MAX0) + (v.y < HT_MIN0);
    over  += (v.z > T_MAX0)  + (v.z < T_MIN0);
    under += (v.z > HT_MAX0) + (v.z < HT_MIN0);
    over  += (v.w > T_MAX0)  + (v.w < T_MIN0);
    under += (v.w > HT_MAX0) + (v.w < HT_MIN0);
}

// One kernel: grid-stride count, block reduce, global atomics; the LAST block
// to finish computes sigma/inv/tmin/tmax and resets the accumulators so the
// kernel is replay-deterministic under CUDA graph capture.
__global__ void __launch_bounds__(256) count_decide_kernel(
        const float4* __restrict__ x4, int nquads, float n) {
    int tid    = blockIdx.x * blockDim.x + threadIdx.x;
    int stride = gridDim.x * blockDim.x;
    int over = 0, under = 0;

    int i = tid;
    for (; i + 3 * stride < nquads; i += 4 * stride) {
        float4 a = x4[i];
        float4 b = x4[i + stride];
        float4 c = x4[i + 2 * stride];
        float4 d = x4[i + 3 * stride];
        count4(a, over, under);
        count4(b, over, under);
        count4(c, over, under);
        count4(d, over, under);
    }
    for (; i < nquads; i += stride) {
        count4(x4[i], over, under);
    }

    over  = __reduce_add_sync(0xffffffffu, over);
    under = __reduce_add_sync(0xffffffffu, under);

    __shared__ int so[8], su[8];
    int warp = threadIdx.x >> 5;
    int lane = threadIdx.x & 31;
    if (lane == 0) { so[warp] = over; su[warp] = under; }
    __syncthreads();

    if (threadIdx.x == 0) {
        int o = 0, u = 0;
#pragma unroll
        for (int w = 0; w < 8; w++) { o += so[w]; u += su[w]; }
        atomicAdd(&g_over,  (unsigned)o);
        atomicAdd(&g_under, (unsigned)u);
        __threadfence();
        unsigned t = atomicAdd(&g_done, 1u);
        if (t == gridDim.x - 1) {
            // All blocks' contributions are visible (fence + ticket order).
            unsigned ov = atomicAdd(&g_over,  0u);
            unsigned un = atomicAdd(&g_under, 0u);
            float overflow  = __uint2float_rn(ov) / n;
            float underflow = __uint2float_rn(un) / n;
            float sigma = 0.25f;
            if (overflow > 0.01f)       sigma = 0.5f;
            else if (underflow < 0.01f) sigma = 0.125f;
            g_qp = make_float4(sigma, 1.0f / sigma,
                               -(sigma * 128.0f), sigma * 128.0f - sigma);
            atomicExch(&g_over,  0u);
            atomicExch(&g_under, 0u);
            __threadfence();
            atomicExch(&g_done,  0u);
        }
    }
}

// --- integer add forced onto the fma pipe: IMAD d = a*one + b ---------------
// `one` is a runtime kernel argument equal to 1; ptxas cannot fold it, so the
// add issues as IMAD (fma pipe) instead of IADD3 (alu pipe).
__device__ __forceinline__ uint32_t addi(uint32_t a, uint32_t one, uint32_t b) {
    uint32_t d;
    asm("mad.lo.u32 %0, %1, %2, %3;" : "=r"(d) : "r"(a), "r"(one), "r"(b));
    return d;
}

__global__ void __launch_bounds__(256) quantize_kernel(const float* __restrict__ x,
                                                       float* __restrict__ out,
                                                       uint32_t k0, uint32_t k1,
                                                       uint32_t one, int n) {
    int t = blockIdx.x * blockDim.x + threadIdx.x;
    int j = t << 2;
    if (j >= n) return;

    const uint32_t ks2 = k0 ^ k1 ^ 0x1BD11BDAu;
    const uint32_t kc1 = ks2 + 1u;
    const uint32_t kc2 = k0  + 2u;
    const uint32_t kc3 = k1  + 3u;
    const uint32_t kc4 = ks2 + 4u;
    const uint32_t kc5 = k0  + 5u;

    float4 qp = g_qp;             // x=sigma, y=inv, z=tmin, w=tmax
    float4 v = *reinterpret_cast<const float4*>(x + j);
    float4 q;

    uint32_t x1b = addi((uint32_t)j, one, k1);   // j + k1

#pragma unroll
    for (int c = 0; c < 4; c++) {
        // threefry2x32 block: key=(k0,k1), counter=(0, j+c)
        uint32_t x0 = k0;                 // 0 + k0
        uint32_t x1 = x1b + (uint32_t)c;  // (j+c) + k1
#define TF_R(r) { x0 = addi(x0, one, x1); x1 = __funnelshift_l(x1, x1, (r)); x1 ^= x0; }
        TF_R(13) TF_R(15) TF_R(26) TF_R(6)
        x0 = addi(x0, one, k1);  x1 = addi(x1, one, kc1);
        TF_R(17) TF_R(29) TF_R(16) TF_R(24)
        x0 = addi(x0, one, ks2); x1 = addi(x1, one, kc2);
        TF_R(13) TF_R(15) TF_R(26) TF_R(6)
        x0 = addi(x0, one, k0);  x1 = addi(x1, one, kc3);
        TF_R(17) TF_R(29) TF_R(16) TF_R(24)
        x0 = addi(x0, one, k1);  x1 = addi(x1, one, kc4);
        TF_R(13) TF_R(15) TF_R(26) TF_R(6)
        x0 = addi(x0, one, ks2); x1 = addi(x1, one, kc5);
#undef TF_R
        uint32_t bits = x0 ^ x1;
        // u = float(bits>>9) * 2^-23  ==  bitcast((bits>>9)|0x3f800000) - 1.0
        // exactly (m < 2^23 so both equal m*2^-23 with no rounding).
        float u = __fmul_rn(__uint2float_rn(bits >> 9), 1.1920928955078125e-7f);
        float a = (&v.x)[c];
        // floor(a/sigma + u) * sigma, clip. a*inv exact (sigma = power of 2).
        float s  = __fadd_rn(__fmul_rn(a, qp.y), u);
        float qv = __fmul_rn(floorf(s), qp.x);
        (&q.x)[c] = fminf(fmaxf(qv, qp.z), qp.w);
    }
    *reinterpret_cast<float4*>(out + j) = q;
}

// --- host-side threefry for key fold ---------------------------------------
static void h_threefry(uint32_t k0, uint32_t k1, uint32_t x0, uint32_t x1,
                       uint32_t& o0, uint32_t& o1) {
    auto rotl = [](uint32_t v, int r) { return (v << r) | (v >> (32 - r)); };
    uint32_t ks[3] = { k0, k1, k0 ^ k1 ^ 0x1BD11BDAu };
    const int R[2][4] = { {13, 15, 26, 6}, {17, 29, 16, 24} };
    x0 += ks[0]; x1 += ks[1];
    for (int i = 0; i < 5; i++) {
        for (int jj = 0; jj < 4; jj++) {
            x0 += x1; x1 = rotl(x1, R[i % 2][jj]); x1 ^= x0;
        }
        x0 += ks[(i + 1) % 3];
        x1 += ks[(i + 2) % 3] + (uint32_t)(i + 1);
    }
    o0 = x0; o1 = x1;
}

extern "C" void kernel_launch(void* const* d_in, const int* in_sizes, int n_in,
                              void* d_out, int out_size) {
    const float* x = (const float*)d_in[0];
    float* out = (float*)d_out;
    int n = in_sizes[0];           // 32*2048*2048 = 134217728

    // key = fold_in(key(42), 0): threefry_2x32(key=[0,42], count=[0,0])
    uint32_t fk0, fk1;
    h_threefry(0u, 42u, 0u, 0u, fk0, fk1);

    int nquads = n >> 2;
    count_decide_kernel<<<2048, 256>>>((const float4*)x, nquads, (float)n);

    int qthreads = (n + 3) >> 2;
    int qblocks = (qthreads + 255) / 256;
    quantize_kernel<<<qblocks, 256>>>(x, out, fk0, fk1, 1u, n);
}